// round 7
// baseline (speedup 1.0000x reference)
#include <cuda_runtime.h>
#include <cstdint>
#include <math.h>

// ----------------------------------------------------------------------------
// StackDevConv, factorized + dst-sorted edges + tf32 mma, occupancy edition.
//   W1 = [Wa | Wb];  A[n] = x[n]@(Wa-Wb)^T + b1 ;  B[n] = x[n]@Wb^T   (fp32)
//   per edge: h = ReLU(A[dst]+B[src]);  msg = h @ W2^T + b2           (tf32 mma)
//   out[n] = segment_max(msg, dst) ; empty -> 0
// sMsg aliases sH (safe: af fragments fully loaded before sMsg writes, fenced
// by an extra barrier) -> 54KB smem -> 3 blocks/SM; cross-block warps hide
// the random-gather latency that intra-block register prefetch couldn't
// (register spill). 4 barriers/tile.
// ----------------------------------------------------------------------------

#define DIMV    64
#define TPB     256
#define PADW    68
#define E_TILE  128
#define MAX_NODES 50000
#define MAX_EDGES 800000

#define SH 68    // sH / sMsg stride
#define SW 72    // sW2 stride -> B-frag LDS conflict-free

__device__ float g_h1[MAX_NODES * DIMV];
__device__ float g_A [MAX_NODES * DIMV];
__device__ float g_B [MAX_NODES * DIMV];
__device__ int   g_count [MAX_NODES];
__device__ int   g_offset[MAX_NODES];
__device__ int   g_src_s[MAX_EDGES];
__device__ int   g_dst_s[MAX_EDGES];

#define PRE_SMEM_FLOATS (64*PADW*3 + 64)
#define PRE_SMEM_BYTES  (PRE_SMEM_FLOATS*4)

// edge smem (4B words): sW2tf[64*SW] + sB2[64] + sH/sMsg[128*SH] + sDst[128]
#define EDGE_SMEM_WORDS (64*SW + 64 + 128*SH + 128)
#define EDGE_SMEM_BYTES (EDGE_SMEM_WORDS*4)

__device__ __forceinline__ void atomic_max_float(float* addr, float value) {
    unsigned int ui = __float_as_uint(value);
    if ((int)ui >= 0) atomicMax((int*)addr, (int)ui);
    else              atomicMin((unsigned int*)addr, ui);
}

__device__ __forceinline__ unsigned int f2tf(float x) {
    unsigned int r;
    asm("cvt.rna.tf32.f32 %0, %1;" : "=r"(r) : "f"(x));
    return r;
}

__global__ void init_neg_inf_kernel(float* p, int n) {
    int i = blockIdx.x * blockDim.x + threadIdx.x;
    if (i < n) ((unsigned int*)p)[i] = 0xFF800000u;
}

__global__ void finalize_kernel(float* p, int n) {
    int i = blockIdx.x * blockDim.x + threadIdx.x;
    if (i < n) { float v = p[i]; if (!isfinite(v)) p[i] = 0.0f; }
}

// ---------------- counting sort by dst ----------------
__global__ void zero_count_kernel(int n_nodes) {
    int i = blockIdx.x * blockDim.x + threadIdx.x;
    if (i < n_nodes) g_count[i] = 0;
}

__global__ void hist_kernel(const int* __restrict__ dst, int n_edges) {
    int i = blockIdx.x * blockDim.x + threadIdx.x;
    if (i < n_edges) atomicAdd(&g_count[dst[i]], 1);
}

__global__ void scan_kernel(int n_nodes) {
    __shared__ int partial[1024];
    const int tid = threadIdx.x;
    const int chunk = (n_nodes + 1023) / 1024;
    const int begin = tid * chunk;
    const int end   = min(begin + chunk, n_nodes);
    int s = 0;
    for (int i = begin; i < end; i++) s += g_count[i];
    partial[tid] = s;
    __syncthreads();
    for (int off = 1; off < 1024; off <<= 1) {
        int v = partial[tid];
        int add = (tid >= off) ? partial[tid - off] : 0;
        __syncthreads();
        partial[tid] = v + add;
        __syncthreads();
    }
    int base = (tid > 0) ? partial[tid - 1] : 0;
    for (int i = begin; i < end; i++) { g_offset[i] = base; base += g_count[i]; }
}

__global__ void scatter_kernel(const int* __restrict__ src,
                               const int* __restrict__ dst, int n_edges) {
    int i = blockIdx.x * blockDim.x + threadIdx.x;
    if (i < n_edges) {
        int d = dst[i];
        int pos = atomicAdd(&g_offset[d], 1);
        g_src_s[pos] = src[i];
        g_dst_s[pos] = d;
    }
}

// ---------------- per-node precompute (fp32, exact) ----------------
__global__ __launch_bounds__(TPB, 3)
void pre_kernel(const float* __restrict__ x,
                const float* __restrict__ W1, const float* __restrict__ b1,
                float* __restrict__ A, float* __restrict__ B,
                int n_nodes, int finite_fix)
{
    extern __shared__ float smem[];
    float* sWdT = smem;
    float* sWbT = sWdT + 64 * PADW;
    float* sB1  = sWbT + 64 * PADW;
    float* sXT  = sB1 + 64;

    const int tid = threadIdx.x;

    for (int i = tid; i < 64 * 64; i += TPB) {
        int c = i >> 6, k = i & 63;
        float wa = W1[c * 128 + k];
        float wb = W1[c * 128 + 64 + k];
        sWdT[k * PADW + c] = wa - wb;
        sWbT[k * PADW + c] = wb;
    }
    if (tid < 64) sB1[tid] = b1[tid];

    const int n0 = blockIdx.x * 64;
    {
        const int e = tid >> 2;
        const int q = tid & 3;
        const int node = n0 + e;
        const float4* xr = (const float4*)(x + (size_t)(node < n_nodes ? node : 0) * DIMV);
        #pragma unroll
        for (int v = 0; v < 4; v++) {
            const int c4 = q * 4 + v;
            float4 a = (node < n_nodes) ? xr[c4] : make_float4(0.f,0.f,0.f,0.f);
            if (finite_fix) {
                if (!isfinite(a.x)) a.x = 0.f;
                if (!isfinite(a.y)) a.y = 0.f;
                if (!isfinite(a.z)) a.z = 0.f;
                if (!isfinite(a.w)) a.w = 0.f;
            }
            const int c = c4 * 4;
            sXT[(c + 0) * PADW + e] = a.x;
            sXT[(c + 1) * PADW + e] = a.y;
            sXT[(c + 2) * PADW + e] = a.z;
            sXT[(c + 3) * PADW + e] = a.w;
        }
    }
    __syncthreads();

    const int ty = tid >> 4, tx = tid & 15;
    const int r = ty * 4, cc = tx * 4;

    float accA[4][4], accB[4][4];
    #pragma unroll
    for (int i = 0; i < 4; i++)
        #pragma unroll
        for (int j = 0; j < 4; j++) { accA[i][j] = sB1[cc + j]; accB[i][j] = 0.f; }

    #pragma unroll 2
    for (int k = 0; k < 64; k++) {
        const float4 xf = *(const float4*)&sXT[k * PADW + r];
        const float4 wd = *(const float4*)&sWdT[k * PADW + cc];
        const float4 wb = *(const float4*)&sWbT[k * PADW + cc];
        const float a0 = xf.x, a1 = xf.y, a2 = xf.z, a3 = xf.w;
        accA[0][0]+=a0*wd.x; accA[0][1]+=a0*wd.y; accA[0][2]+=a0*wd.z; accA[0][3]+=a0*wd.w;
        accA[1][0]+=a1*wd.x; accA[1][1]+=a1*wd.y; accA[1][2]+=a1*wd.z; accA[1][3]+=a1*wd.w;
        accA[2][0]+=a2*wd.x; accA[2][1]+=a2*wd.y; accA[2][2]+=a2*wd.z; accA[2][3]+=a2*wd.w;
        accA[3][0]+=a3*wd.x; accA[3][1]+=a3*wd.y; accA[3][2]+=a3*wd.z; accA[3][3]+=a3*wd.w;
        accB[0][0]+=a0*wb.x; accB[0][1]+=a0*wb.y; accB[0][2]+=a0*wb.z; accB[0][3]+=a0*wb.w;
        accB[1][0]+=a1*wb.x; accB[1][1]+=a1*wb.y; accB[1][2]+=a1*wb.z; accB[1][3]+=a1*wb.w;
        accB[2][0]+=a2*wb.x; accB[2][1]+=a2*wb.y; accB[2][2]+=a2*wb.z; accB[2][3]+=a2*wb.w;
        accB[3][0]+=a3*wb.x; accB[3][1]+=a3*wb.y; accB[3][2]+=a3*wb.z; accB[3][3]+=a3*wb.w;
    }

    #pragma unroll
    for (int i = 0; i < 4; i++) {
        const int node = n0 + r + i;
        if (node < n_nodes) {
            *(float4*)&A[(size_t)node * DIMV + cc] =
                make_float4(accA[i][0], accA[i][1], accA[i][2], accA[i][3]);
            *(float4*)&B[(size_t)node * DIMV + cc] =
                make_float4(accB[i][0], accB[i][1], accB[i][2], accB[i][3]);
        }
    }
}

// ---------------- edge kernel: tf32 mma, aliased buffers, 3 blocks/SM ----
__global__ __launch_bounds__(TPB, 3)
void edge_kernel(const float* __restrict__ A, const float* __restrict__ B,
                 const float* __restrict__ W2, const float* __restrict__ b2,
                 float* __restrict__ out, int n_edges)
{
    extern __shared__ unsigned int usmem[];
    unsigned int* sW2tf = usmem;                       // [k][n] tf32, stride SW
    float*        sB2   = (float*)(sW2tf + 64 * SW);
    unsigned int* sH    = (unsigned int*)(sB2 + 64);   // [e][k] tf32, stride SH
    float*        sMsg  = (float*)sH;                  // ALIAS: [e][n], stride SH
    int*          sDst  = (int*)(sH + 128 * SH);

    const int tid  = threadIdx.x;
    const int wid  = tid >> 5;
    const int lane = tid & 31;
    const int grp  = lane >> 2;
    const int qd   = lane & 3;

    for (int i = tid; i < 64 * 64; i += TPB) {
        int n = i >> 6, k = i & 63;
        sW2tf[k * SW + n] = f2tf(W2[n * 64 + k]);
    }
    if (tid < 64) sB2[tid] = b2[tid];
    __syncthreads();

    const int ty = tid >> 4, tx = tid & 15;
    const int r = ty * 8, cc = tx * 4;

    const int n_tiles = (n_edges + E_TILE - 1) / E_TILE;

    for (int tile = blockIdx.x; tile < n_tiles; tile += gridDim.x) {
        const int e0 = tile * E_TILE;

        // ---- gather + ReLU -> sH[e][k] (tf32), 2 threads/edge ----
        {
            const int e = tid >> 1;
            const int q = tid & 1;
            const int eg = e0 + e;
            const bool valid = (eg < n_edges);
            int s = 0, d = 0;
            if (valid) { s = g_src_s[eg]; d = g_dst_s[eg]; }
            if (q == 0) sDst[e] = valid ? d : -1;
            const float4* a4 = (const float4*)(A + (size_t)d * DIMV) + q * 8;
            const float4* b4 = (const float4*)(B + (size_t)s * DIMV) + q * 8;
            uint4* hp = (uint4*)&sH[e * SH] + q * 8;
            #pragma unroll
            for (int v = 0; v < 8; v++) {
                float4 a = valid ? a4[v] : make_float4(0.f,0.f,0.f,0.f);
                float4 b = valid ? b4[v] : make_float4(0.f,0.f,0.f,0.f);
                uint4 hv;
                hv.x = f2tf(fmaxf(a.x + b.x, 0.f));
                hv.y = f2tf(fmaxf(a.y + b.y, 0.f));
                hv.z = f2tf(fmaxf(a.z + b.z, 0.f));
                hv.w = f2tf(fmaxf(a.w + b.w, 0.f));
                hp[v] = hv;
            }
        }
        __syncthreads();   // sync1: sH/sDst ready

        // ---- load all A fragments, then fence before sMsg overwrites sH ----
        const int m0 = wid * 16;
        unsigned int af[8][4];
        #pragma unroll
        for (int ks = 0; ks < 8; ks++) {
            const int k0 = ks * 8;
            af[ks][0] = sH[(m0 + grp    ) * SH + k0 + qd    ];
            af[ks][1] = sH[(m0 + grp + 8) * SH + k0 + qd    ];
            af[ks][2] = sH[(m0 + grp    ) * SH + k0 + qd + 4];
            af[ks][3] = sH[(m0 + grp + 8) * SH + k0 + qd + 4];
        }
        // pre-read dst chain for scatter (sDst stable this tile)
        int rd[8];
        #pragma unroll
        for (int i = 0; i < 8; i++) rd[i] = sDst[r + i];
        __syncthreads();   // sync2: all af loaded; sH reusable as sMsg

        // ---- tf32 mma -> sMsg (aliases sH) ----
        #pragma unroll
        for (int nt = 0; nt < 8; nt++) {
            const int n0c = nt * 8;
            float c0 = 0.f, c1 = 0.f, c2 = 0.f, c3 = 0.f;
            #pragma unroll
            for (int ks = 0; ks < 8; ks++) {
                const int k0 = ks * 8;
                unsigned int b0 = sW2tf[(k0 + qd    ) * SW + n0c + grp];
                unsigned int b1 = sW2tf[(k0 + qd + 4) * SW + n0c + grp];
                asm volatile(
                    "mma.sync.aligned.m16n8k8.row.col.f32.tf32.tf32.f32 "
                    "{%0,%1,%2,%3}, {%4,%5,%6,%7}, {%8,%9}, {%0,%1,%2,%3};"
                    : "+f"(c0), "+f"(c1), "+f"(c2), "+f"(c3)
                    : "r"(af[ks][0]), "r"(af[ks][1]), "r"(af[ks][2]), "r"(af[ks][3]),
                      "r"(b0), "r"(b1));
            }
            const int col = n0c + 2 * qd;
            const float bb0 = sB2[col], bb1 = sB2[col + 1];
            *(float2*)&sMsg[(m0 + grp    ) * SH + col] = make_float2(c0 + bb0, c1 + bb1);
            *(float2*)&sMsg[(m0 + grp + 8) * SH + col] = make_float2(c2 + bb0, c3 + bb1);
        }
        __syncthreads();   // sync3: sMsg ready

        // ---- scatter: run-merge within 8-edge chains, atomics at run ends ----
        {
            float4 cur = *(const float4*)&sMsg[r * SH + cc];
            #pragma unroll
            for (int i = 0; i < 8; i++) {
                const int de = rd[i];
                const bool last = (i == 7) || (rd[i + 1] != de);
                if (!last) {
                    const float4 nx = *(const float4*)&sMsg[(r + i + 1) * SH + cc];
                    cur.x = fmaxf(cur.x, nx.x);
                    cur.y = fmaxf(cur.y, nx.y);
                    cur.z = fmaxf(cur.z, nx.z);
                    cur.w = fmaxf(cur.w, nx.w);
                } else {
                    if (de >= 0) {
                        float* op = out + (size_t)de * DIMV + cc;
                        atomic_max_float(op + 0, cur.x);
                        atomic_max_float(op + 1, cur.y);
                        atomic_max_float(op + 2, cur.z);
                        atomic_max_float(op + 3, cur.w);
                    }
                    if (i < 7)
                        cur = *(const float4*)&sMsg[(r + i + 1) * SH + cc];
                }
            }
        }
        __syncthreads();   // sync4: scatter done; sMsg reusable as sH(t+1)
    }
}

extern "C" void kernel_launch(void* const* d_in, const int* in_sizes, int n_in,
                              void* d_out, int out_size)
{
    const float* x   = (const float*)d_in[0];
    const int*   ei  = (const int*)d_in[1];
    const float* W1a = (const float*)d_in[2];
    const float* b1a = (const float*)d_in[3];
    const float* W2a = (const float*)d_in[4];
    const float* b2a = (const float*)d_in[5];
    const float* W1b = (const float*)d_in[6];
    const float* b1b = (const float*)d_in[7];
    const float* W2b = (const float*)d_in[8];
    const float* b2b = (const float*)d_in[9];

    const int n_nodes = in_sizes[0] / DIMV;
    const int n_edges = in_sizes[1] / 2;
    const int* src = ei;
    const int* dst = ei + n_edges;

    float* out = (float*)d_out;
    float *h1, *Abuf, *Bbuf;
    cudaGetSymbolAddress((void**)&h1,   g_h1);
    cudaGetSymbolAddress((void**)&Abuf, g_A);
    cudaGetSymbolAddress((void**)&Bbuf, g_B);

    cudaFuncSetAttribute(pre_kernel,
                         cudaFuncAttributeMaxDynamicSharedMemorySize, PRE_SMEM_BYTES);
    cudaFuncSetAttribute(edge_kernel,
                         cudaFuncAttributeMaxDynamicSharedMemorySize, EDGE_SMEM_BYTES);

    const int n_feat = n_nodes * DIMV;
    const int init_blocks = (n_feat + TPB - 1) / TPB;
    const int pre_blocks  = (n_nodes + 63) / 64;
    const int edge_blocks = 148 * 3;
    const int eb = (n_edges + TPB - 1) / TPB;
    const int nb = (n_nodes + TPB - 1) / TPB;

    // ---- counting sort by dst (once; reused by both layers) ----
    zero_count_kernel<<<nb, TPB>>>(n_nodes);
    hist_kernel<<<eb, TPB>>>(dst, n_edges);
    scan_kernel<<<1, 1024>>>(n_nodes);
    scatter_kernel<<<eb, TPB>>>(src, dst, n_edges);

    // ---- layer 1 ----
    pre_kernel<<<pre_blocks, TPB, PRE_SMEM_BYTES>>>(x, W1a, b1a, Abuf, Bbuf, n_nodes, 0);
    init_neg_inf_kernel<<<init_blocks, TPB>>>(h1, n_feat);
    edge_kernel<<<edge_blocks, TPB, EDGE_SMEM_BYTES>>>(Abuf, Bbuf, W2a, b2a, h1, n_edges);

    // ---- layer 2 (h1 finalize fused via finite_fix) ----
    pre_kernel<<<pre_blocks, TPB, PRE_SMEM_BYTES>>>(h1, W1b, b1b, Abuf, Bbuf, n_nodes, 1);
    init_neg_inf_kernel<<<init_blocks, TPB>>>(out, n_feat);
    edge_kernel<<<edge_blocks, TPB, EDGE_SMEM_BYTES>>>(Abuf, Bbuf, W2b, b2b, out, n_edges);
    finalize_kernel<<<init_blocks, TPB>>>(out, n_feat);
}